// round 1
// baseline (speedup 1.0000x reference)
#include <cuda_runtime.h>
#include <math.h>

#define NN   10000
#define NE   250000
#define FF   128
#define HFD  512      // HEADS*FEAT
#define NRBF 50

// ---------------- scratch (static device globals; no allocation) ----------------
__device__ float g_x[NN * FF];                    //  5.1 MB  layernormed s
__device__ float g_qkv[NN * 3 * HFD];             // 61.4 MB  [q|k|v] per node
__device__ float g_rbf[(size_t)NE * NRBF];        // 50 MB
__device__ float g_unit[(size_t)NE * 3];          //  3 MB
__device__ float g_dkdv[(size_t)NE * 2 * HFD];    //  1 GB    [dk|dv] per edge
__device__ float g_msg[(size_t)NE * HFD];         // 512 MB
__device__ float g_eout[(size_t)NE * 3 * FF];     // 384 MB   per-edge out

// ---------------- zero output ----------------
__global__ void zero_kernel(float* __restrict__ p, int n) {
    int i = blockIdx.x * blockDim.x + threadIdx.x;
    if (i < n) p[i] = 0.f;
}

// ---------------- layernorm: 1 block / node, 128 threads ----------------
__global__ void __launch_bounds__(128) ln_kernel(const float* __restrict__ s,
                                                 const float* __restrict__ gam,
                                                 const float* __restrict__ bet,
                                                 float* __restrict__ x) {
    int n = blockIdx.x, t = threadIdx.x;
    float v = s[(size_t)n * FF + t];
    float s1 = v, s2 = v * v;
    #pragma unroll
    for (int o = 16; o; o >>= 1) {
        s1 += __shfl_down_sync(0xffffffffu, s1, o);
        s2 += __shfl_down_sync(0xffffffffu, s2, o);
    }
    __shared__ float p1[4], p2[4], mv[2];
    if ((t & 31) == 0) { p1[t >> 5] = s1; p2[t >> 5] = s2; }
    __syncthreads();
    if (t == 0) {
        float a = p1[0] + p1[1] + p1[2] + p1[3];
        float c = p2[0] + p2[1] + p2[2] + p2[3];
        float m = a / 128.f;
        mv[0] = m;
        mv[1] = rsqrtf(c / 128.f - m * m + 1e-5f);
    }
    __syncthreads();
    x[(size_t)n * FF + t] = (v - mv[0]) * mv[1] * gam[t] + bet[t];
}

// ---------------- edge prep: dist, unit, rbf ----------------
__global__ void edge_prep(const float* __restrict__ r,
                          float* __restrict__ rbf,
                          float* __restrict__ unit) {
    int e = blockIdx.x * blockDim.x + threadIdx.x;
    if (e >= NE) return;
    float x = r[3 * e], y = r[3 * e + 1], z = r[3 * e + 2];
    float d = sqrtf(x * x + y * y + z * z + 3e-15f);
    float inv = 1.f / d;
    unit[3 * e] = x * inv; unit[3 * e + 1] = y * inv; unit[3 * e + 2] = z * inv;
    const float width = 5.0f / 49.0f;
    const float gam = 0.5f / (width * width);
    #pragma unroll
    for (int k = 0; k < NRBF; k++) {
        float dd = d - (float)k * width;
        rbf[(size_t)e * NRBF + k] = expf(-gam * dd * dd);
    }
}

// ---------------- generic SGEMM: C = act(A[MxK] @ B[KxN] + bias) ----------------
// 128x128 block tile, BK=8, 256 threads, 8x8 per thread. ACT: 0=none, 1=silu.
template <int ACT>
__global__ void __launch_bounds__(256) sgemm(const float* __restrict__ A,
                                             const float* __restrict__ B,
                                             const float* __restrict__ bias,
                                             float* __restrict__ C,
                                             int M, int N, int K, int ldc) {
    __shared__ float As[8][128];
    __shared__ float Bs[8][128];

    int tid = threadIdx.x;
    int ty = tid >> 4, tx = tid & 15;
    int row0 = blockIdx.y * 128;
    int col0 = blockIdx.x * 128;

    float acc[8][8];
    #pragma unroll
    for (int i = 0; i < 8; i++)
        #pragma unroll
        for (int j = 0; j < 8; j++) acc[i][j] = 0.f;

    int lm = tid >> 1;            // 0..127
    int lk = (tid & 1) * 4;       // 0 or 4
    int bk = tid >> 5;            // 0..7
    int bn = (tid & 31) * 4;

    for (int kk = 0; kk < K; kk += 8) {
        int m = row0 + lm;
        #pragma unroll
        for (int i = 0; i < 4; i++) {
            int k = kk + lk + i;
            As[lk + i][lm] = (k < K && m < M) ? A[(size_t)m * K + k] : 0.f;
        }
        {
            int k = kk + bk;
            const float* bp = B + (size_t)k * N + col0 + bn;
            bool ok = (k < K);
            #pragma unroll
            for (int i = 0; i < 4; i++) Bs[bk][bn + i] = ok ? bp[i] : 0.f;
        }
        __syncthreads();
        #pragma unroll
        for (int k = 0; k < 8; k++) {
            float a[8], b[8];
            #pragma unroll
            for (int i = 0; i < 8; i++) a[i] = As[k][ty * 8 + i];
            #pragma unroll
            for (int j = 0; j < 8; j++) b[j] = Bs[k][tx * 8 + j];
            #pragma unroll
            for (int i = 0; i < 8; i++)
                #pragma unroll
                for (int j = 0; j < 8; j++) acc[i][j] += a[i] * b[j];
        }
        __syncthreads();
    }

    #pragma unroll
    for (int i = 0; i < 8; i++) {
        int row = row0 + ty * 8 + i;
        if (row >= M) continue;
        #pragma unroll
        for (int j = 0; j < 8; j++) {
            int col = col0 + tx * 8 + j;
            float v = acc[i][j] + bias[col];
            if (ACT) v = v / (1.f + expf(-v));
            C[(size_t)row * ldc + col] = v;
        }
    }
}

// ---------------- attn + msg: 1 block / edge, 128 threads ----------------
__global__ void __launch_bounds__(128) attn_msg(const float* __restrict__ qkv,
                                                const float* __restrict__ dkdv,
                                                const int* __restrict__ nbrs,
                                                float* __restrict__ msg) {
    int e = blockIdx.x;
    int t = threadIdx.x;
    int i = nbrs[2 * e], j = nbrs[2 * e + 1];
    const float* q  = qkv + (size_t)i * 1536;
    const float* kp = qkv + (size_t)j * 1536 + 512;
    const float* vp = qkv + (size_t)j * 1536 + 1024;
    const float* dk = dkdv + (size_t)e * 1024;
    const float* dv = dk + 512;

    float p[4];
    #pragma unroll
    for (int h = 0; h < 4; h++) {
        int c = h * 128 + t;
        p[h] = q[c] * kp[c] * dk[c];
    }
    #pragma unroll
    for (int o = 16; o; o >>= 1)
        #pragma unroll
        for (int h = 0; h < 4; h++) p[h] += __shfl_down_sync(0xffffffffu, p[h], o);

    __shared__ float part[4][4];
    __shared__ float attn[4];
    int w = t >> 5;
    if ((t & 31) == 0)
        #pragma unroll
        for (int h = 0; h < 4; h++) part[h][w] = p[h];
    __syncthreads();
    if (t < 4) {
        float s = part[t][0] + part[t][1] + part[t][2] + part[t][3];
        attn[t] = s / (1.f + expf(-s));   // silu
    }
    __syncthreads();
    #pragma unroll
    for (int h = 0; h < 4; h++) {
        int c = h * 128 + t;
        msg[(size_t)e * 512 + c] = vp[c] * dv[c] * attn[h];
    }
}

// ---------------- scatter with atomics: 1 block / edge, 128 threads ----------------
__global__ void __launch_bounds__(128) scatter_kernel(const float* __restrict__ eout,
                                                      const float* __restrict__ unit,
                                                      const float* __restrict__ v_j,
                                                      const int* __restrict__ nbrs,
                                                      float* __restrict__ ds,
                                                      float* __restrict__ dvout) {
    int e = blockIdx.x;
    int f = threadIdx.x;
    int i = nbrs[2 * e], j = nbrs[2 * e + 1];
    const float* o = eout + (size_t)e * 384;
    float s0 = o[f], s1 = o[128 + f], s2 = o[256 + f];
    float ux = unit[3 * e], uy = unit[3 * e + 1], uz = unit[3 * e + 2];
    const float* vj = v_j + ((size_t)j * FF + f) * 3;

    atomicAdd(&ds[(size_t)i * FF + f], s1);
    float* dvp = dvout + ((size_t)i * FF + f) * 3;
    atomicAdd(dvp + 0, s2 * ux + s0 * vj[0]);
    atomicAdd(dvp + 1, s2 * uy + s0 * vj[1]);
    atomicAdd(dvp + 2, s2 * uz + s0 * vj[2]);
}

// ---------------- launch ----------------
extern "C" void kernel_launch(void* const* d_in, const int* in_sizes, int n_in,
                              void* d_out, int out_size) {
    const float* s_j  = (const float*)d_in[0];
    const float* v_j  = (const float*)d_in[1];
    const float* r_ij = (const float*)d_in[2];
    const int*   nbrs = (const int*)  d_in[3];
    const float* ln_g = (const float*)d_in[4];
    const float* ln_b = (const float*)d_in[5];
    const float* Wq   = (const float*)d_in[6];
    const float* bq   = (const float*)d_in[7];
    const float* Wk   = (const float*)d_in[8];
    const float* bk   = (const float*)d_in[9];
    const float* Wv   = (const float*)d_in[10];
    const float* bv   = (const float*)d_in[11];
    const float* Wdk  = (const float*)d_in[12];
    const float* bdk  = (const float*)d_in[13];
    const float* Wdv  = (const float*)d_in[14];
    const float* bdv  = (const float*)d_in[15];
    const float* Wd   = (const float*)d_in[16];
    const float* bd   = (const float*)d_in[17];
    float* out = (float*)d_out;

    float *x, *qkv, *rbf, *unit, *dkdv, *msg, *eout;
    cudaGetSymbolAddress((void**)&x,    g_x);
    cudaGetSymbolAddress((void**)&qkv,  g_qkv);
    cudaGetSymbolAddress((void**)&rbf,  g_rbf);
    cudaGetSymbolAddress((void**)&unit, g_unit);
    cudaGetSymbolAddress((void**)&dkdv, g_dkdv);
    cudaGetSymbolAddress((void**)&msg,  g_msg);
    cudaGetSymbolAddress((void**)&eout, g_eout);

    const int OUT_ELEMS = NN * FF * 4;   // 1.28M ds + 3.84M dv
    zero_kernel<<<(OUT_ELEMS + 255) / 256, 256>>>(out, OUT_ELEMS);

    ln_kernel<<<NN, 128>>>(s_j, ln_g, ln_b, x);

    // qkv projections: M=10000, N=512 each, K=128, ldc=1536
    dim3 gq(4, (NN + 127) / 128);
    sgemm<0><<<gq, 256>>>(x, Wq, bq, qkv,        NN, 512, 128, 1536);
    sgemm<0><<<gq, 256>>>(x, Wk, bk, qkv + 512,  NN, 512, 128, 1536);
    sgemm<0><<<gq, 256>>>(x, Wv, bv, qkv + 1024, NN, 512, 128, 1536);

    edge_prep<<<(NE + 127) / 128, 128>>>(r_ij, rbf, unit);

    // dk, dv: M=250000, N=512 each, K=50, silu epilogue, ldc=1024
    dim3 ge(4, (NE + 127) / 128);
    sgemm<1><<<ge, 256>>>(rbf, Wdk, bdk, dkdv,       NE, 512, NRBF, 1024);
    sgemm<1><<<ge, 256>>>(rbf, Wdv, bdv, dkdv + 512, NE, 512, NRBF, 1024);

    attn_msg<<<NE, 128>>>(qkv, dkdv, nbrs, msg);

    // out = msg @ Wd + bd : M=250000, N=384, K=512
    dim3 go(3, (NE + 127) / 128);
    sgemm<0><<<go, 256>>>(msg, Wd, bd, eout, NE, 384, 512, 384);

    scatter_kernel<<<NE, 128>>>(eout, unit, v_j, nbrs, out, out + NN * FF);
}

// round 2
// speedup vs baseline: 1.3820x; 1.3820x over previous
#include <cuda_runtime.h>
#include <math.h>

#define NN   10000
#define NE   250000
#define FF   128
#define HFD  512
#define NRBF 50
#define RBFP 56   // padded rbf stride (multiple of 8)

typedef unsigned long long ull;

// ---------------- scratch ----------------
__device__ float g_x[NN * FF];
__device__ float g_qkv[NN * 3 * HFD];
__device__ float g_rbf[(size_t)NE * RBFP];
__device__ float g_unit[(size_t)NE * 3];
__device__ float g_dkdv[(size_t)NE * 2 * HFD];
__device__ float g_msg[(size_t)NE * HFD];
__device__ float g_eout[(size_t)NE * 3 * FF];

#define FMA2(acc, a, b) asm("fma.rn.f32x2 %0, %1, %2, %0;" : "+l"(acc) : "l"(a), "l"(b))
#define PACK2(dst, f)   asm("mov.b64 %0, {%1, %1};" : "=l"(dst) : "f"(f))
#define UNPACK2(lo, hi, v) asm("mov.b64 {%0, %1}, %2;" : "=f"(lo), "=f"(hi) : "l"(v))

__global__ void zero_kernel(float* __restrict__ p, int n) {
    int i = blockIdx.x * blockDim.x + threadIdx.x;
    if (i < n) p[i] = 0.f;
}

__global__ void __launch_bounds__(128) ln_kernel(const float* __restrict__ s,
                                                 const float* __restrict__ gam,
                                                 const float* __restrict__ bet,
                                                 float* __restrict__ x) {
    int n = blockIdx.x, t = threadIdx.x;
    float v = s[(size_t)n * FF + t];
    float s1 = v, s2 = v * v;
    #pragma unroll
    for (int o = 16; o; o >>= 1) {
        s1 += __shfl_down_sync(0xffffffffu, s1, o);
        s2 += __shfl_down_sync(0xffffffffu, s2, o);
    }
    __shared__ float p1[4], p2[4], mv[2];
    if ((t & 31) == 0) { p1[t >> 5] = s1; p2[t >> 5] = s2; }
    __syncthreads();
    if (t == 0) {
        float a = p1[0] + p1[1] + p1[2] + p1[3];
        float c = p2[0] + p2[1] + p2[2] + p2[3];
        float m = a / 128.f;
        mv[0] = m;
        mv[1] = rsqrtf(c / 128.f - m * m + 1e-5f);
    }
    __syncthreads();
    x[(size_t)n * FF + t] = (v - mv[0]) * mv[1] * gam[t] + bet[t];
}

__global__ void edge_prep(const float* __restrict__ r,
                          float* __restrict__ rbf,
                          float* __restrict__ unit) {
    int e = blockIdx.x * blockDim.x + threadIdx.x;
    if (e >= NE) return;
    float x = r[3 * e], y = r[3 * e + 1], z = r[3 * e + 2];
    float d = sqrtf(x * x + y * y + z * z + 3e-15f);
    float inv = 1.f / d;
    unit[3 * e] = x * inv; unit[3 * e + 1] = y * inv; unit[3 * e + 2] = z * inv;
    const float width = 5.0f / 49.0f;
    const float gam = 0.5f / (width * width);
    #pragma unroll
    for (int k = 0; k < RBFP; k++) {
        float dd = d - (float)k * width;
        rbf[(size_t)e * RBFP + k] = (k < NRBF) ? expf(-gam * dd * dd) : 0.f;
    }
}

// ---------------- SGEMM with f32x2 FFMA, double-buffered smem ----------------
// C[M x N] = act(A[M x Kpad](lda) @ B[Kreal x N] + bias), 128x128 tile, BK=8.
template <int ACT>
__global__ void __launch_bounds__(256, 2)
sgemm2(const float* __restrict__ A, const float* __restrict__ B,
       const float* __restrict__ bias, float* __restrict__ C,
       int M, int N, int Kreal, int Kpad, int lda, int ldc) {
    __shared__ float As[2][8][128];
    __shared__ float Bs[2][8][128];

    int t  = threadIdx.x;
    int ty = t >> 4, tx = t & 15;
    int row0 = blockIdx.y * 128;
    int col0 = blockIdx.x * 128;

    // A loads: thread -> row t>>1 (0..127), float4 at col (t&1)*4
    int arow = t >> 1;
    int acol = (t & 1) * 4;
    int am   = min(row0 + arow, M - 1);
    const float* Aptr = A + (size_t)am * lda + acol;

    // B loads: thread -> k t>>5 (0..7), float4 at col (t&31)*4
    int bk = t >> 5;
    int bn = (t & 31) * 4;

    float4 ar, br;
    ar = *(const float4*)(Aptr);
    if (bk < Kreal) br = *(const float4*)(B + (size_t)bk * N + col0 + bn);
    else            br = make_float4(0.f, 0.f, 0.f, 0.f);

    As[0][acol + 0][arow] = ar.x;
    As[0][acol + 1][arow] = ar.y;
    As[0][acol + 2][arow] = ar.z;
    As[0][acol + 3][arow] = ar.w;
    *(float4*)&Bs[0][bk][bn] = br;
    __syncthreads();

    ull acc[8][4];
    #pragma unroll
    for (int i = 0; i < 8; i++)
        #pragma unroll
        for (int j = 0; j < 4; j++) acc[i][j] = 0ULL;

    int nstage = Kpad >> 3;
    for (int s = 0; s < nstage; s++) {
        int cur = s & 1, nxt = cur ^ 1;
        bool more = (s + 1 < nstage);
        if (more) {
            int kk = (s + 1) << 3;
            ar = *(const float4*)(Aptr + kk);
            int kb = kk + bk;
            if (kb < Kreal) br = *(const float4*)(B + (size_t)kb * N + col0 + bn);
            else            br = make_float4(0.f, 0.f, 0.f, 0.f);
        }
        #pragma unroll
        for (int k = 0; k < 8; k++) {
            float4 a0 = *(float4*)&As[cur][k][ty * 8];
            float4 a1 = *(float4*)&As[cur][k][ty * 8 + 4];
            ulonglong2 b0 = *(ulonglong2*)&Bs[cur][k][tx * 8];
            ulonglong2 b1 = *(ulonglong2*)&Bs[cur][k][tx * 8 + 4];
            ull a2[8];
            PACK2(a2[0], a0.x); PACK2(a2[1], a0.y);
            PACK2(a2[2], a0.z); PACK2(a2[3], a0.w);
            PACK2(a2[4], a1.x); PACK2(a2[5], a1.y);
            PACK2(a2[6], a1.z); PACK2(a2[7], a1.w);
            #pragma unroll
            for (int i = 0; i < 8; i++) {
                FMA2(acc[i][0], a2[i], b0.x);
                FMA2(acc[i][1], a2[i], b0.y);
                FMA2(acc[i][2], a2[i], b1.x);
                FMA2(acc[i][3], a2[i], b1.y);
            }
        }
        if (more) {
            As[nxt][acol + 0][arow] = ar.x;
            As[nxt][acol + 1][arow] = ar.y;
            As[nxt][acol + 2][arow] = ar.z;
            As[nxt][acol + 3][arow] = ar.w;
            *(float4*)&Bs[nxt][bk][bn] = br;
        }
        __syncthreads();
    }

    // epilogue
    int colb = col0 + tx * 8;
    float4 bs0 = *(const float4*)(bias + colb);
    float4 bs1 = *(const float4*)(bias + colb + 4);
    #pragma unroll
    for (int i = 0; i < 8; i++) {
        int row = row0 + ty * 8 + i;
        if (row >= M) continue;
        float v[8];
        UNPACK2(v[0], v[1], acc[i][0]);
        UNPACK2(v[2], v[3], acc[i][1]);
        UNPACK2(v[4], v[5], acc[i][2]);
        UNPACK2(v[6], v[7], acc[i][3]);
        v[0] += bs0.x; v[1] += bs0.y; v[2] += bs0.z; v[3] += bs0.w;
        v[4] += bs1.x; v[5] += bs1.y; v[6] += bs1.z; v[7] += bs1.w;
        if (ACT) {
            #pragma unroll
            for (int j = 0; j < 8; j++) v[j] = v[j] / (1.f + expf(-v[j]));
        }
        float* cp = C + (size_t)row * ldc + colb;
        *(float4*)cp       = make_float4(v[0], v[1], v[2], v[3]);
        *(float4*)(cp + 4) = make_float4(v[4], v[5], v[6], v[7]);
    }
}

// ---------------- attn + msg ----------------
__global__ void __launch_bounds__(128) attn_msg(const float* __restrict__ qkv,
                                                const float* __restrict__ dkdv,
                                                const int* __restrict__ nbrs,
                                                float* __restrict__ msg) {
    int e = blockIdx.x;
    int t = threadIdx.x;
    int i = nbrs[2 * e], j = nbrs[2 * e + 1];
    const float* q  = qkv + (size_t)i * 1536;
    const float* kp = qkv + (size_t)j * 1536 + 512;
    const float* vp = qkv + (size_t)j * 1536 + 1024;
    const float* dk = dkdv + (size_t)e * 1024;
    const float* dv = dk + 512;

    float p[4];
    #pragma unroll
    for (int h = 0; h < 4; h++) {
        int c = h * 128 + t;
        p[h] = q[c] * kp[c] * dk[c];
    }
    #pragma unroll
    for (int o = 16; o; o >>= 1)
        #pragma unroll
        for (int h = 0; h < 4; h++) p[h] += __shfl_down_sync(0xffffffffu, p[h], o);

    __shared__ float part[4][4];
    __shared__ float attn[4];
    int w = t >> 5;
    if ((t & 31) == 0)
        #pragma unroll
        for (int h = 0; h < 4; h++) part[h][w] = p[h];
    __syncthreads();
    if (t < 4) {
        float s = part[t][0] + part[t][1] + part[t][2] + part[t][3];
        attn[t] = s / (1.f + expf(-s));
    }
    __syncthreads();
    #pragma unroll
    for (int h = 0; h < 4; h++) {
        int c = h * 128 + t;
        msg[(size_t)e * 512 + c] = vp[c] * dv[c] * attn[h];
    }
}

// ---------------- scatter ----------------
__global__ void __launch_bounds__(128) scatter_kernel(const float* __restrict__ eout,
                                                      const float* __restrict__ unit,
                                                      const float* __restrict__ v_j,
                                                      const int* __restrict__ nbrs,
                                                      float* __restrict__ ds,
                                                      float* __restrict__ dvout) {
    int e = blockIdx.x;
    int f = threadIdx.x;
    int i = nbrs[2 * e], j = nbrs[2 * e + 1];
    const float* o = eout + (size_t)e * 384;
    float s0 = o[f], s1 = o[128 + f], s2 = o[256 + f];
    float ux = unit[3 * e], uy = unit[3 * e + 1], uz = unit[3 * e + 2];
    const float* vj = v_j + ((size_t)j * FF + f) * 3;

    atomicAdd(&ds[(size_t)i * FF + f], s1);
    float* dvp = dvout + ((size_t)i * FF + f) * 3;
    atomicAdd(dvp + 0, s2 * ux + s0 * vj[0]);
    atomicAdd(dvp + 1, s2 * uy + s0 * vj[1]);
    atomicAdd(dvp + 2, s2 * uz + s0 * vj[2]);
}

// ---------------- launch ----------------
extern "C" void kernel_launch(void* const* d_in, const int* in_sizes, int n_in,
                              void* d_out, int out_size) {
    const float* s_j  = (const float*)d_in[0];
    const float* v_j  = (const float*)d_in[1];
    const float* r_ij = (const float*)d_in[2];
    const int*   nbrs = (const int*)  d_in[3];
    const float* ln_g = (const float*)d_in[4];
    const float* ln_b = (const float*)d_in[5];
    const float* Wq   = (const float*)d_in[6];
    const float* bq   = (const float*)d_in[7];
    const float* Wk   = (const float*)d_in[8];
    const float* bk   = (const float*)d_in[9];
    const float* Wv   = (const float*)d_in[10];
    const float* bv   = (const float*)d_in[11];
    const float* Wdk  = (const float*)d_in[12];
    const float* bdk  = (const float*)d_in[13];
    const float* Wdv  = (const float*)d_in[14];
    const float* bdv  = (const float*)d_in[15];
    const float* Wd   = (const float*)d_in[16];
    const float* bd   = (const float*)d_in[17];
    float* out = (float*)d_out;

    float *x, *qkv, *rbf, *unit, *dkdv, *msg, *eout;
    cudaGetSymbolAddress((void**)&x,    g_x);
    cudaGetSymbolAddress((void**)&qkv,  g_qkv);
    cudaGetSymbolAddress((void**)&rbf,  g_rbf);
    cudaGetSymbolAddress((void**)&unit, g_unit);
    cudaGetSymbolAddress((void**)&dkdv, g_dkdv);
    cudaGetSymbolAddress((void**)&msg,  g_msg);
    cudaGetSymbolAddress((void**)&eout, g_eout);

    const int OUT_ELEMS = NN * FF * 4;
    zero_kernel<<<(OUT_ELEMS + 255) / 256, 256>>>(out, OUT_ELEMS);

    ln_kernel<<<NN, 128>>>(s_j, ln_g, ln_b, x);

    dim3 gq(4, (NN + 127) / 128);
    sgemm2<0><<<gq, 256>>>(x, Wq, bq, qkv,        NN, 512, 128, 128, 128, 1536);
    sgemm2<0><<<gq, 256>>>(x, Wk, bk, qkv + 512,  NN, 512, 128, 128, 128, 1536);
    sgemm2<0><<<gq, 256>>>(x, Wv, bv, qkv + 1024, NN, 512, 128, 128, 128, 1536);

    edge_prep<<<(NE + 127) / 128, 128>>>(r_ij, rbf, unit);

    dim3 ge(4, (NE + 127) / 128);
    sgemm2<1><<<ge, 256>>>(rbf, Wdk, bdk, dkdv,       NE, 512, NRBF, RBFP, RBFP, 1024);
    sgemm2<1><<<ge, 256>>>(rbf, Wdv, bdv, dkdv + 512, NE, 512, NRBF, RBFP, RBFP, 1024);

    attn_msg<<<NE, 128>>>(qkv, dkdv, nbrs, msg);

    dim3 go(3, (NE + 127) / 128);
    sgemm2<0><<<go, 256>>>(msg, Wd, bd, eout, NE, 384, 512, 512, 512, 384);

    scatter_kernel<<<NE, 128>>>(eout, unit, v_j, nbrs, out, out + NN * FF);
}

// round 4
// speedup vs baseline: 1.4040x; 1.0160x over previous
#include <cuda_runtime.h>
#include <math.h>
#include <stdint.h>

#define NN   10000
#define NE   250000
#define FF   128
#define NRBF 50
#define RBFP 56

typedef unsigned long long ull;

// ---------------- scratch ----------------
__device__ float g_x[NN * FF];
__device__ float g_qkv[NN * 3 * 512];
__device__ float g_rbf[(size_t)NE * RBFP];
__device__ float g_unit[(size_t)NE * 3];
__device__ float g_dkdv[(size_t)NE * 1024];
__device__ float g_msg[(size_t)NE * 512];

#define FMA2(acc, a, b) asm("fma.rn.f32x2 %0, %1, %2, %0;" : "+l"(acc) : "l"(a), "l"(b))
#define PACK2(dst, f)   asm("mov.b64 %0, {%1, %1};" : "=l"(dst) : "f"(f))
#define UNPACK2(lo, hi, v) asm("mov.b64 {%0, %1}, %2;" : "=f"(lo), "=f"(hi) : "l"(v))

__device__ __forceinline__ uint32_t tf32r(float x) {
    uint32_t r;
    asm("cvt.rna.tf32.f32 %0, %1;" : "=r"(r) : "f"(x));
    return r;
}

#define MMA_TF32(c, a0, a1, a2, a3, b0, b1)                               \
    asm volatile("mma.sync.aligned.m16n8k8.row.col.f32.tf32.tf32.f32 "    \
        "{%0,%1,%2,%3}, {%4,%5,%6,%7}, {%8,%9}, {%0,%1,%2,%3};"           \
        : "+f"((c)[0]), "+f"((c)[1]), "+f"((c)[2]), "+f"((c)[3])          \
        : "r"(a0), "r"(a1), "r"(a2), "r"(a3), "r"(b0), "r"(b1))

// ================= small kernels =================
__global__ void zero_kernel(float* __restrict__ p, int n) {
    int i = blockIdx.x * blockDim.x + threadIdx.x;
    if (i < n) p[i] = 0.f;
}

__global__ void __launch_bounds__(128) ln_kernel(const float* __restrict__ s,
                                                 const float* __restrict__ gam,
                                                 const float* __restrict__ bet,
                                                 float* __restrict__ x) {
    int n = blockIdx.x, t = threadIdx.x;
    float v = s[(size_t)n * FF + t];
    float s1 = v, s2 = v * v;
    #pragma unroll
    for (int o = 16; o; o >>= 1) {
        s1 += __shfl_down_sync(0xffffffffu, s1, o);
        s2 += __shfl_down_sync(0xffffffffu, s2, o);
    }
    __shared__ float p1[4], p2[4], mv[2];
    if ((t & 31) == 0) { p1[t >> 5] = s1; p2[t >> 5] = s2; }
    __syncthreads();
    if (t == 0) {
        float a = p1[0] + p1[1] + p1[2] + p1[3];
        float c = p2[0] + p2[1] + p2[2] + p2[3];
        float m = a / 128.f;
        mv[0] = m;
        mv[1] = rsqrtf(c / 128.f - m * m + 1e-5f);
    }
    __syncthreads();
    x[(size_t)n * FF + t] = (v - mv[0]) * mv[1] * gam[t] + bet[t];
}

__global__ void edge_prep(const float* __restrict__ r,
                          float* __restrict__ rbf,
                          float* __restrict__ unit) {
    int e = blockIdx.x * blockDim.x + threadIdx.x;
    if (e >= NE) return;
    float x = r[3 * e], y = r[3 * e + 1], z = r[3 * e + 2];
    float d = sqrtf(x * x + y * y + z * z + 3e-15f);
    float inv = 1.f / d;
    unit[3 * e] = x * inv; unit[3 * e + 1] = y * inv; unit[3 * e + 2] = z * inv;
    const float width = 5.0f / 49.0f;
    const float gam = 0.5f / (width * width);
    #pragma unroll
    for (int k = 0; k < RBFP; k++) {
        float dd = d - (float)k * width;
        rbf[(size_t)e * RBFP + k] = (k < NRBF) ? expf(-gam * dd * dd) : 0.f;
    }
}

// ================= f32x2 SGEMM (qkv only) =================
template <int ACT>
__global__ void __launch_bounds__(256, 2)
sgemm2(const float* __restrict__ A, const float* __restrict__ B,
       const float* __restrict__ bias, float* __restrict__ C,
       int M, int N, int Kreal, int Kpad, int lda, int ldc) {
    __shared__ float As[2][8][128];
    __shared__ float Bs[2][8][128];

    int t  = threadIdx.x;
    int ty = t >> 4, tx = t & 15;
    int row0 = blockIdx.y * 128;
    int col0 = blockIdx.x * 128;

    int arow = t >> 1;
    int acol = (t & 1) * 4;
    int am   = min(row0 + arow, M - 1);
    const float* Aptr = A + (size_t)am * lda + acol;

    int bk = t >> 5;
    int bn = (t & 31) * 4;

    float4 ar, br;
    ar = *(const float4*)(Aptr);
    if (bk < Kreal) br = *(const float4*)(B + (size_t)bk * N + col0 + bn);
    else            br = make_float4(0.f, 0.f, 0.f, 0.f);

    As[0][acol + 0][arow] = ar.x;
    As[0][acol + 1][arow] = ar.y;
    As[0][acol + 2][arow] = ar.z;
    As[0][acol + 3][arow] = ar.w;
    *(float4*)&Bs[0][bk][bn] = br;
    __syncthreads();

    ull acc[8][4];
    #pragma unroll
    for (int i = 0; i < 8; i++)
        #pragma unroll
        for (int j = 0; j < 4; j++) acc[i][j] = 0ULL;

    int nstage = Kpad >> 3;
    for (int s = 0; s < nstage; s++) {
        int cur = s & 1, nxt = cur ^ 1;
        bool more = (s + 1 < nstage);
        if (more) {
            int kk = (s + 1) << 3;
            ar = *(const float4*)(Aptr + kk);
            int kb = kk + bk;
            if (kb < Kreal) br = *(const float4*)(B + (size_t)kb * N + col0 + bn);
            else            br = make_float4(0.f, 0.f, 0.f, 0.f);
        }
        #pragma unroll
        for (int k = 0; k < 8; k++) {
            float4 a0 = *(float4*)&As[cur][k][ty * 8];
            float4 a1 = *(float4*)&As[cur][k][ty * 8 + 4];
            ulonglong2 b0 = *(ulonglong2*)&Bs[cur][k][tx * 8];
            ulonglong2 b1 = *(ulonglong2*)&Bs[cur][k][tx * 8 + 4];
            ull a2[8];
            PACK2(a2[0], a0.x); PACK2(a2[1], a0.y);
            PACK2(a2[2], a0.z); PACK2(a2[3], a0.w);
            PACK2(a2[4], a1.x); PACK2(a2[5], a1.y);
            PACK2(a2[6], a1.z); PACK2(a2[7], a1.w);
            #pragma unroll
            for (int i = 0; i < 8; i++) {
                FMA2(acc[i][0], a2[i], b0.x);
                FMA2(acc[i][1], a2[i], b0.y);
                FMA2(acc[i][2], a2[i], b1.x);
                FMA2(acc[i][3], a2[i], b1.y);
            }
        }
        if (more) {
            As[nxt][acol + 0][arow] = ar.x;
            As[nxt][acol + 1][arow] = ar.y;
            As[nxt][acol + 2][arow] = ar.z;
            As[nxt][acol + 3][arow] = ar.w;
            *(float4*)&Bs[nxt][bk][bn] = br;
        }
        __syncthreads();
    }

    int colb = col0 + tx * 8;
    float4 bs0 = *(const float4*)(bias + colb);
    float4 bs1 = *(const float4*)(bias + colb + 4);
    #pragma unroll
    for (int i = 0; i < 8; i++) {
        int row = row0 + ty * 8 + i;
        if (row >= M) continue;
        float v[8];
        UNPACK2(v[0], v[1], acc[i][0]);
        UNPACK2(v[2], v[3], acc[i][1]);
        UNPACK2(v[4], v[5], acc[i][2]);
        UNPACK2(v[6], v[7], acc[i][3]);
        v[0] += bs0.x; v[1] += bs0.y; v[2] += bs0.z; v[3] += bs0.w;
        v[4] += bs1.x; v[5] += bs1.y; v[6] += bs1.z; v[7] += bs1.w;
        if (ACT) {
            #pragma unroll
            for (int j = 0; j < 8; j++) v[j] = v[j] / (1.f + expf(-v[j]));
        }
        float* cp = C + (size_t)row * ldc + colb;
        *(float4*)cp       = make_float4(v[0], v[1], v[2], v[3]);
        *(float4*)(cp + 4) = make_float4(v[4], v[5], v[6], v[7]);
    }
}

// ================= attn + msg =================
__global__ void __launch_bounds__(128) attn_msg(const float* __restrict__ qkv,
                                                const float* __restrict__ dkdv,
                                                const int* __restrict__ nbrs,
                                                float* __restrict__ msg) {
    int e = blockIdx.x;
    int t = threadIdx.x;
    int i = nbrs[2 * e], j = nbrs[2 * e + 1];
    const float* q  = qkv + (size_t)i * 1536;
    const float* kp = qkv + (size_t)j * 1536 + 512;
    const float* vp = qkv + (size_t)j * 1536 + 1024;
    const float* dk = dkdv + (size_t)e * 1024;
    const float* dv = dk + 512;

    float p[4];
    #pragma unroll
    for (int h = 0; h < 4; h++) {
        int c = h * 128 + t;
        p[h] = q[c] * kp[c] * dk[c];
    }
    #pragma unroll
    for (int o = 16; o; o >>= 1)
        #pragma unroll
        for (int h = 0; h < 4; h++) p[h] += __shfl_down_sync(0xffffffffu, p[h], o);

    __shared__ float part[4][4];
    __shared__ float attn[4];
    int w = t >> 5;
    if ((t & 31) == 0)
        #pragma unroll
        for (int h = 0; h < 4; h++) part[h][w] = p[h];
    __syncthreads();
    if (t < 4) {
        float s = part[t][0] + part[t][1] + part[t][2] + part[t][3];
        attn[t] = s / (1.f + expf(-s));
    }
    __syncthreads();
    #pragma unroll
    for (int h = 0; h < 4; h++) {
        int c = h * 128 + t;
        msg[(size_t)e * 512 + c] = vp[c] * dv[c] * attn[h];
    }
}

// ================= tf32 mma.sync GEMM =================
// CTA 128x128, 8 warps (4M x 2N), warp 32Mx64N, mma m16n8k8, BK=32.
// Smem layout: element (row, kk) at [row*36 + (kk&7)*4 + (kk>>3)] (tf32 bits).
// EPI=0: C = silu(A@B + bias) stored at C[r*ldc + n0 + nc].
// EPI=1: fused scatter; blockIdx.x selects output slice (0:s0*v_j, 1:s1, 2:s2*unit).
#define SROW 36
#define SBUF (128 * SROW)

template <int EPI>
__global__ void __launch_bounds__(256)
mma_gemm(const float* __restrict__ A, const float* __restrict__ B,
         const float* __restrict__ bias, float* __restrict__ C, int ldc,
         const float* __restrict__ unit, const float* __restrict__ v_j,
         const int* __restrict__ nbrs, float* __restrict__ ds,
         float* __restrict__ dvout,
         int M, int Nld, int Kb, int lda, int nstage) {
    extern __shared__ float sm[];
    float* Asm = sm;                // 2 * SBUF
    float* Bsm = sm + 2 * SBUF;     // 2 * SBUF

    const int tid = threadIdx.x;
    const int wid = tid >> 5, lid = tid & 31;
    const int gq = lid >> 2, tig = lid & 3;
    const int wM = wid >> 1, wN = wid & 1;
    const int row0 = blockIdx.y * 128;
    const int n0   = blockIdx.x * 128;

    float acc[2][8][4];
    #pragma unroll
    for (int a = 0; a < 2; a++)
        #pragma unroll
        for (int b = 0; b < 8; b++)
            #pragma unroll
            for (int c = 0; c < 4; c++) acc[a][b][c] = 0.f;

    // staging coordinates
    const int akq   = tid & 7;        // A: k-quad 0..7, rows (tid>>3)+32i
    const int arow0 = tid >> 3;
    const int bkk   = tid & 31;       // B: k 0..31, n-quads (tid>>5)+8i
    const int bn40  = tid >> 5;
    // permuted column indices for A's 4 scalars (kk = akq*4 + c)
    int pA[4];
    #pragma unroll
    for (int c = 0; c < 4; c++) {
        int kkc = akq * 4 + c;
        pA[c] = ((kkc & 7) << 2) + (kkc >> 3);
    }
    const int pB = ((bkk & 7) << 2) + (bkk >> 3);

    float4 aR[4], bR[4];

    #define LOADS(s_) {                                                        \
        int k0_ = (s_) * 32;                                                   \
        _Pragma("unroll")                                                      \
        for (int i = 0; i < 4; i++) {                                          \
            int gr = min(row0 + arow0 + i * 32, M - 1);                        \
            aR[i] = *(const float4*)(A + (size_t)gr * lda + k0_ + akq * 4);    \
        }                                                                      \
        if (k0_ + bkk < Kb) {                                                  \
            const float* bp = B + (size_t)(k0_ + bkk) * Nld + n0;              \
            _Pragma("unroll")                                                  \
            for (int i = 0; i < 4; i++)                                        \
                bR[i] = *(const float4*)(bp + (bn40 + i * 8) * 4);             \
        } else {                                                               \
            _Pragma("unroll")                                                  \
            for (int i = 0; i < 4; i++) bR[i] = make_float4(0.f,0.f,0.f,0.f);  \
        }                                                                      \
    }

    #define STORES(buf_) {                                                     \
        float* ab = Asm + (buf_) * SBUF;                                       \
        _Pragma("unroll")                                                      \
        for (int i = 0; i < 4; i++) {                                          \
            float* d = ab + (arow0 + i * 32) * SROW;                           \
            d[pA[0]] = __uint_as_float(tf32r(aR[i].x));                        \
            d[pA[1]] = __uint_as_float(tf32r(aR[i].y));                        \
            d[pA[2]] = __uint_as_float(tf32r(aR[i].z));                        \
            d[pA[3]] = __uint_as_float(tf32r(aR[i].w));                        \
        }                                                                      \
        float* bb = Bsm + (buf_) * SBUF + pB;                                  \
        _Pragma("unroll")                                                      \
        for (int i = 0; i < 4; i++) {                                          \
            int nb = (bn40 + i * 8) * 4;                                       \
            bb[(nb + 0) * SROW] = __uint_as_float(tf32r(bR[i].x));             \
            bb[(nb + 1) * SROW] = __uint_as_float(tf32r(bR[i].y));             \
            bb[(nb + 2) * SROW] = __uint_as_float(tf32r(bR[i].z));             \
            bb[(nb + 3) * SROW] = __uint_as_float(tf32r(bR[i].w));             \
        }                                                                      \
    }

    LOADS(0);
    STORES(0);
    __syncthreads();

    for (int s = 0; s < nstage; s++) {
        int cur = s & 1;
        bool more = (s + 1 < nstage);
        if (more) LOADS(s + 1);

        const float* Ab = Asm + cur * SBUF;
        const float* Bb = Bsm + cur * SBUF;
        uint4 aP[2][4];
        #pragma unroll
        for (int mf = 0; mf < 2; mf++) {
            int rb = wM * 32 + mf * 16;
            aP[mf][0] = *(const uint4*)(Ab + (rb + gq) * SROW + tig * 4);
            aP[mf][1] = *(const uint4*)(Ab + (rb + gq + 8) * SROW + tig * 4);
            aP[mf][2] = *(const uint4*)(Ab + (rb + gq) * SROW + tig * 4 + 16);
            aP[mf][3] = *(const uint4*)(Ab + (rb + gq + 8) * SROW + tig * 4 + 16);
        }
        #pragma unroll
        for (int nf = 0; nf < 8; nf++) {
            int nn = wN * 64 + nf * 8 + gq;
            uint4 b0 = *(const uint4*)(Bb + nn * SROW + tig * 4);
            uint4 b1 = *(const uint4*)(Bb + nn * SROW + tig * 4 + 16);
            #pragma unroll
            for (int mf = 0; mf < 2; mf++) {
                MMA_TF32(acc[mf][nf], aP[mf][0].x, aP[mf][1].x, aP[mf][2].x, aP[mf][3].x, b0.x, b1.x);
                MMA_TF32(acc[mf][nf], aP[mf][0].y, aP[mf][1].y, aP[mf][2].y, aP[mf][3].y, b0.y, b1.y);
                MMA_TF32(acc[mf][nf], aP[mf][0].z, aP[mf][1].z, aP[mf][2].z, aP[mf][3].z, b0.z, b1.z);
                MMA_TF32(acc[mf][nf], aP[mf][0].w, aP[mf][1].w, aP[mf][2].w, aP[mf][3].w, b0.w, b1.w);
            }
        }
        __syncthreads();
        if (more) {
            STORES((s + 1) & 1);
            __syncthreads();
        }
    }

    if (EPI == 0) {
        #pragma unroll
        for (int mf = 0; mf < 2; mf++)
        #pragma unroll
        for (int rs = 0; rs < 2; rs++) {
            int r = row0 + wM * 32 + mf * 16 + gq + rs * 8;
            if (r >= M) continue;
            #pragma unroll
            for (int nf = 0; nf < 8; nf++) {
                int nc = wN * 64 + nf * 8 + tig * 2;
                float v0 = acc[mf][nf][rs * 2 + 0] + __ldg(bias + n0 + nc);
                float v1 = acc[mf][nf][rs * 2 + 1] + __ldg(bias + n0 + nc + 1);
                v0 = v0 / (1.f + expf(-v0));
                v1 = v1 / (1.f + expf(-v1));
                *(float2*)(C + (size_t)r * ldc + n0 + nc) = make_float2(v0, v1);
            }
        }
    } else {
        int nt = blockIdx.x;   // 0: s0*v_j, 1: s1, 2: s2*unit
        #pragma unroll
        for (int mf = 0; mf < 2; mf++)
        #pragma unroll
        for (int rs = 0; rs < 2; rs++) {
            int e = row0 + wM * 32 + mf * 16 + gq + rs * 8;
            if (e >= M) continue;
            int ii = nbrs[2 * e], jj = nbrs[2 * e + 1];
            float ux = 0.f, uy = 0.f, uz = 0.f;
            if (nt == 2) { ux = unit[3 * e]; uy = unit[3 * e + 1]; uz = unit[3 * e + 2]; }
            #pragma unroll
            for (int nf = 0; nf < 8; nf++) {
                #pragma unroll
                for (int c01 = 0; c01 < 2; c01++) {
                    int nc = wN * 64 + nf * 8 + tig * 2 + c01;
                    float val = acc[mf][nf][rs * 2 + c01] + __ldg(bias + n0 + nc);
                    if (nt == 1) {
                        atomicAdd(ds + (size_t)ii * FF + nc, val);
                    } else if (nt == 0) {
                        const float* vj = v_j + ((size_t)jj * FF + nc) * 3;
                        float* dv = dvout + ((size_t)ii * FF + nc) * 3;
                        atomicAdd(dv + 0, val * vj[0]);
                        atomicAdd(dv + 1, val * vj[1]);
                        atomicAdd(dv + 2, val * vj[2]);
                    } else {
                        float* dv = dvout + ((size_t)ii * FF + nc) * 3;
                        atomicAdd(dv + 0, val * ux);
                        atomicAdd(dv + 1, val * uy);
                        atomicAdd(dv + 2, val * uz);
                    }
                }
            }
        }
    }
}

// ================= launch =================
extern "C" void kernel_launch(void* const* d_in, const int* in_sizes, int n_in,
                              void* d_out, int out_size) {
    const float* s_j  = (const float*)d_in[0];
    const float* v_j  = (const float*)d_in[1];
    const float* r_ij = (const float*)d_in[2];
    const int*   nbrs = (const int*)  d_in[3];
    const float* ln_g = (const float*)d_in[4];
    const float* ln_b = (const float*)d_in[5];
    const float* Wq   = (const float*)d_in[6];
    const float* bq   = (const float*)d_in[7];
    const float* Wk   = (const float*)d_in[8];
    const float* bk   = (const float*)d_in[9];
    const float* Wv   = (const float*)d_in[10];
    const float* bv   = (const float*)d_in[11];
    const float* Wdk  = (const float*)d_in[12];
    const float* bdk  = (const float*)d_in[13];
    const float* Wdv  = (const float*)d_in[14];
    const float* bdv  = (const float*)d_in[15];
    const float* Wd   = (const float*)d_in[16];
    const float* bd   = (const float*)d_in[17];
    float* out = (float*)d_out;

    float *x, *qkv, *rbf, *unit, *dkdv, *msg;
    cudaGetSymbolAddress((void**)&x,    g_x);
    cudaGetSymbolAddress((void**)&qkv,  g_qkv);
    cudaGetSymbolAddress((void**)&rbf,  g_rbf);
    cudaGetSymbolAddress((void**)&unit, g_unit);
    cudaGetSymbolAddress((void**)&dkdv, g_dkdv);
    cudaGetSymbolAddress((void**)&msg,  g_msg);

    const int MMA_SMEM = 4 * SBUF * 4;   // 73728 bytes
    cudaFuncSetAttribute(mma_gemm<0>, cudaFuncAttributeMaxDynamicSharedMemorySize, MMA_SMEM);
    cudaFuncSetAttribute(mma_gemm<1>, cudaFuncAttributeMaxDynamicSharedMemorySize, MMA_SMEM);

    const int OUT_ELEMS = NN * FF * 4;
    zero_kernel<<<(OUT_ELEMS + 255) / 256, 256>>>(out, OUT_ELEMS);

    ln_kernel<<<NN, 128>>>(s_j, ln_g, ln_b, x);

    dim3 gq4(4, (NN + 127) / 128);
    sgemm2<0><<<gq4, 256>>>(x, Wq, bq, qkv,        NN, 512, 128, 128, 128, 1536);
    sgemm2<0><<<gq4, 256>>>(x, Wk, bk, qkv + 512,  NN, 512, 128, 128, 128, 1536);
    sgemm2<0><<<gq4, 256>>>(x, Wv, bv, qkv + 1024, NN, 512, 128, 128, 128, 1536);

    edge_prep<<<(NE + 127) / 128, 128>>>(r_ij, rbf, unit);

    int mtiles = (NE + 127) / 128;   // 1954
    // dk/dv: M=NE, N=512, K=50 (A padded to 56, 2 stages of 32)
    dim3 ge(4, mtiles);
    mma_gemm<0><<<ge, 256, MMA_SMEM>>>(rbf, Wdk, bdk, dkdv, 1024,
                                       nullptr, nullptr, nullptr, nullptr, nullptr,
                                       NE, 512, 50, RBFP, 2);
    mma_gemm<0><<<ge, 256, MMA_SMEM>>>(rbf, Wdv, bdv, dkdv + 512, 1024,
                                       nullptr, nullptr, nullptr, nullptr, nullptr,
                                       NE, 512, 50, RBFP, 2);

    attn_msg<<<NE, 128>>>(qkv, dkdv, nbrs, msg);

    // big GEMM (msg @ Wd) + fused scatter, N=384 (3 slices), K=512 (16 stages)
    dim3 gb(3, mtiles);
    mma_gemm<1><<<gb, 256, MMA_SMEM>>>(msg, Wd, bd, nullptr, 0,
                                       unit, v_j, nbrs, out, out + NN * FF,
                                       NE, 384, 512, 512, 16);
}

// round 5
// speedup vs baseline: 2.2341x; 1.5912x over previous
#include <cuda_runtime.h>
#include <cuda_fp16.h>
#include <math.h>
#include <stdint.h>

#define NN   10000
#define NE   250000
#define FF   128
#define NRBF 50
#define RBFP 64   // padded rbf stride (halves)

typedef unsigned long long ull;

// ---------------- scratch ----------------
__device__ float  g_x[NN * FF];
__device__ float  g_qkv[NN * 3 * 512];
__device__ __half g_rbf[(size_t)NE * RBFP];
__device__ float  g_unit[(size_t)NE * 3];
__device__ __half g_dkdv[(size_t)NE * 1024];
__device__ __half g_msg[(size_t)NE * 512];

#define FMA2(acc, a, b) asm("fma.rn.f32x2 %0, %1, %2, %0;" : "+l"(acc) : "l"(a), "l"(b))
#define PACK2(dst, f)   asm("mov.b64 %0, {%1, %1};" : "=l"(dst) : "f"(f))
#define UNPACK2(lo, hi, v) asm("mov.b64 {%0, %1}, %2;" : "=f"(lo), "=f"(hi) : "l"(v))

__device__ __forceinline__ uint32_t smem_u32(const void* p) {
    uint32_t a;
    asm("{ .reg .u64 t; cvta.to.shared.u64 t, %1; cvt.u32.u64 %0, t; }" : "=r"(a) : "l"(p));
    return a;
}

#define MMA_F16(c, a0, a1, a2, a3, b0, b1)                                \
    asm volatile("mma.sync.aligned.m16n8k16.row.col.f32.f16.f16.f32 "     \
        "{%0,%1,%2,%3}, {%4,%5,%6,%7}, {%8,%9}, {%0,%1,%2,%3};"           \
        : "+f"((c)[0]), "+f"((c)[1]), "+f"((c)[2]), "+f"((c)[3])          \
        : "r"(a0), "r"(a1), "r"(a2), "r"(a3), "r"(b0), "r"(b1))

#define CP_ASYNC16(dst, src) \
    asm volatile("cp.async.ca.shared.global [%0], [%1], 16;" :: "r"(dst), "l"(src))
#define CP_COMMIT() asm volatile("cp.async.commit_group;" ::: "memory")
#define CP_WAIT0()  asm volatile("cp.async.wait_group 0;" ::: "memory")

// ================= small kernels =================
__global__ void zero_kernel(float* __restrict__ p, int n) {
    int i = blockIdx.x * blockDim.x + threadIdx.x;
    if (i < n) p[i] = 0.f;
}

__global__ void __launch_bounds__(128) ln_kernel(const float* __restrict__ s,
                                                 const float* __restrict__ gam,
                                                 const float* __restrict__ bet,
                                                 float* __restrict__ x) {
    int n = blockIdx.x, t = threadIdx.x;
    float v = s[(size_t)n * FF + t];
    float s1 = v, s2 = v * v;
    #pragma unroll
    for (int o = 16; o; o >>= 1) {
        s1 += __shfl_down_sync(0xffffffffu, s1, o);
        s2 += __shfl_down_sync(0xffffffffu, s2, o);
    }
    __shared__ float p1[4], p2[4], mv[2];
    if ((t & 31) == 0) { p1[t >> 5] = s1; p2[t >> 5] = s2; }
    __syncthreads();
    if (t == 0) {
        float a = p1[0] + p1[1] + p1[2] + p1[3];
        float c = p2[0] + p2[1] + p2[2] + p2[3];
        float m = a / 128.f;
        mv[0] = m;
        mv[1] = rsqrtf(c / 128.f - m * m + 1e-5f);
    }
    __syncthreads();
    x[(size_t)n * FF + t] = (v - mv[0]) * mv[1] * gam[t] + bet[t];
}

__global__ void edge_prep(const float* __restrict__ r,
                          __half* __restrict__ rbf,
                          float* __restrict__ unit) {
    int e = blockIdx.x * blockDim.x + threadIdx.x;
    if (e >= NE) return;
    float x = r[3 * e], y = r[3 * e + 1], z = r[3 * e + 2];
    float d = sqrtf(x * x + y * y + z * z + 3e-15f);
    float inv = 1.f / d;
    unit[3 * e] = x * inv; unit[3 * e + 1] = y * inv; unit[3 * e + 2] = z * inv;
    const float width = 5.0f / 49.0f;
    const float gam = 0.5f / (width * width);
    #pragma unroll
    for (int k = 0; k < RBFP; k++) {
        float dd = d - (float)k * width;
        float v = (k < NRBF) ? expf(-gam * dd * dd) : 0.f;
        rbf[(size_t)e * RBFP + k] = __float2half_rn(v);
    }
}

// ================= qkv: fused 3-way f32x2 SGEMM =================
__global__ void __launch_bounds__(256, 2)
qkv_gemm(const float* __restrict__ Xin,
         const float* __restrict__ Wq, const float* __restrict__ Wk,
         const float* __restrict__ Wv,
         const float* __restrict__ bq, const float* __restrict__ bk,
         const float* __restrict__ bv,
         float* __restrict__ qkvout) {
    const int M = NN, N = 512, K = 128, lda = 128, ldc = 1536;
    int which = blockIdx.x >> 2;
    const float* B    = (which == 0) ? Wq : ((which == 1) ? Wk : Wv);
    const float* bias = (which == 0) ? bq : ((which == 1) ? bk : bv);
    float* C = qkvout + which * 512;
    int col0 = (blockIdx.x & 3) * 128;
    int row0 = blockIdx.y * 128;

    __shared__ float As[2][8][128];
    __shared__ float Bs[2][8][128];

    int t  = threadIdx.x;
    int ty = t >> 4, tx = t & 15;

    int arow = t >> 1;
    int acol = (t & 1) * 4;
    int am   = min(row0 + arow, M - 1);
    const float* Aptr = Xin + (size_t)am * lda + acol;

    int bk_ = t >> 5;
    int bn  = (t & 31) * 4;

    float4 ar, br;
    ar = *(const float4*)(Aptr);
    br = *(const float4*)(B + (size_t)bk_ * N + col0 + bn);

    As[0][acol + 0][arow] = ar.x;
    As[0][acol + 1][arow] = ar.y;
    As[0][acol + 2][arow] = ar.z;
    As[0][acol + 3][arow] = ar.w;
    *(float4*)&Bs[0][bk_][bn] = br;
    __syncthreads();

    ull acc[8][4];
    #pragma unroll
    for (int i = 0; i < 8; i++)
        #pragma unroll
        for (int j = 0; j < 4; j++) acc[i][j] = 0ULL;

    const int nstage = K >> 3;
    for (int s = 0; s < nstage; s++) {
        int cur = s & 1, nxt = cur ^ 1;
        bool more = (s + 1 < nstage);
        if (more) {
            int kk = (s + 1) << 3;
            ar = *(const float4*)(Aptr + kk);
            br = *(const float4*)(B + (size_t)(kk + bk_) * N + col0 + bn);
        }
        #pragma unroll
        for (int k = 0; k < 8; k++) {
            float4 a0 = *(float4*)&As[cur][k][ty * 8];
            float4 a1 = *(float4*)&As[cur][k][ty * 8 + 4];
            ulonglong2 b0 = *(ulonglong2*)&Bs[cur][k][tx * 8];
            ulonglong2 b1 = *(ulonglong2*)&Bs[cur][k][tx * 8 + 4];
            ull a2[8];
            PACK2(a2[0], a0.x); PACK2(a2[1], a0.y);
            PACK2(a2[2], a0.z); PACK2(a2[3], a0.w);
            PACK2(a2[4], a1.x); PACK2(a2[5], a1.y);
            PACK2(a2[6], a1.z); PACK2(a2[7], a1.w);
            #pragma unroll
            for (int i = 0; i < 8; i++) {
                FMA2(acc[i][0], a2[i], b0.x);
                FMA2(acc[i][1], a2[i], b0.y);
                FMA2(acc[i][2], a2[i], b1.x);
                FMA2(acc[i][3], a2[i], b1.y);
            }
        }
        if (more) {
            As[nxt][acol + 0][arow] = ar.x;
            As[nxt][acol + 1][arow] = ar.y;
            As[nxt][acol + 2][arow] = ar.z;
            As[nxt][acol + 3][arow] = ar.w;
            *(float4*)&Bs[nxt][bk_][bn] = br;
        }
        __syncthreads();
    }

    int colb = col0 + tx * 8;
    float4 bs0 = *(const float4*)(bias + colb);
    float4 bs1 = *(const float4*)(bias + colb + 4);
    #pragma unroll
    for (int i = 0; i < 8; i++) {
        int row = row0 + ty * 8 + i;
        if (row >= M) continue;
        float v[8];
        UNPACK2(v[0], v[1], acc[i][0]);
        UNPACK2(v[2], v[3], acc[i][1]);
        UNPACK2(v[4], v[5], acc[i][2]);
        UNPACK2(v[6], v[7], acc[i][3]);
        v[0] += bs0.x; v[1] += bs0.y; v[2] += bs0.z; v[3] += bs0.w;
        v[4] += bs1.x; v[5] += bs1.y; v[6] += bs1.z; v[7] += bs1.w;
        float* cp = C + (size_t)row * ldc + colb;
        *(float4*)cp       = make_float4(v[0], v[1], v[2], v[3]);
        *(float4*)(cp + 4) = make_float4(v[4], v[5], v[6], v[7]);
    }
}

// ================= attn + msg (half dkdv -> half msg) =================
__global__ void __launch_bounds__(128) attn_msg(const float* __restrict__ qkv,
                                                const __half* __restrict__ dkdv,
                                                const int* __restrict__ nbrs,
                                                __half* __restrict__ msg) {
    int e = blockIdx.x;
    int t = threadIdx.x;
    int i = nbrs[2 * e], j = nbrs[2 * e + 1];
    const float*  q  = qkv + (size_t)i * 1536;
    const float*  kp = qkv + (size_t)j * 1536 + 512;
    const float*  vp = qkv + (size_t)j * 1536 + 1024;
    const __half* dk = dkdv + (size_t)e * 1024;
    const __half* dv = dk + 512;

    float p[4];
    #pragma unroll
    for (int h = 0; h < 4; h++) {
        int c = h * 128 + t;
        p[h] = q[c] * kp[c] * __half2float(dk[c]);
    }
    #pragma unroll
    for (int o = 16; o; o >>= 1)
        #pragma unroll
        for (int h = 0; h < 4; h++) p[h] += __shfl_down_sync(0xffffffffu, p[h], o);

    __shared__ float part[4][4];
    __shared__ float attn[4];
    int w = t >> 5;
    if ((t & 31) == 0)
        #pragma unroll
        for (int h = 0; h < 4; h++) part[h][w] = p[h];
    __syncthreads();
    if (t < 4) {
        float s = part[t][0] + part[t][1] + part[t][2] + part[t][3];
        attn[t] = s / (1.f + expf(-s));
    }
    __syncthreads();
    #pragma unroll
    for (int h = 0; h < 4; h++) {
        int c = h * 128 + t;
        msg[(size_t)e * 512 + c] =
            __float2half_rn(vp[c] * __half2float(dv[c]) * attn[h]);
    }
}

// ================= fp16 mma GEMM =================
// CTA 128 rows x (NSLICE*128) cols, mma m16n8k16, BK=32 (16 kpairs/stage).
// A: half [M x lda], staged via cp.async into [row][kpair] (row stride 20 u32).
// B: float [Kb x Nld], staged transposed+converted into [n][perm(kpair)].
// EPI=0: C(half) = silu(A@B + bias) at cols n0.  EPI=1: fused scatter (3 slices).
#define SROWU 20
#define ABUFU (128 * SROWU)   // 2560 u32 per buffer

template <int EPI, int NSLICE>
__global__ void __launch_bounds__(256)
mma_fp16(const __half* __restrict__ A, const float* __restrict__ B,
         const float* __restrict__ bias, __half* __restrict__ C, int ldc,
         const float* __restrict__ unit, const float* __restrict__ v_j,
         const int* __restrict__ nbrs, float* __restrict__ ds,
         float* __restrict__ dvout,
         int M, int Nld, int Kb, int lda, int nstage) {
    extern __shared__ uint32_t sm[];
    uint32_t* Abuf = sm;                 // [2][ABUFU]
    uint32_t* Bbuf = sm + 2 * ABUFU;     // [NSLICE][2][ABUFU] (sl*2+buf)
    const uint32_t sA = smem_u32(sm);

    const int tid = threadIdx.x;
    const int wid = tid >> 5, lid = tid & 31;
    const int gq = lid >> 2, tig = lid & 3;
    const int wM = wid >> 1, wN = wid & 1;
    const int row0 = (EPI ? blockIdx.x : blockIdx.y) * 128;
    const int n0s  = (EPI ? 0 : blockIdx.x * 128);

    float acc[NSLICE][2][8][4];
    #pragma unroll
    for (int s = 0; s < NSLICE; s++)
        #pragma unroll
        for (int a = 0; a < 2; a++)
            #pragma unroll
            for (int b = 0; b < 8; b++)
                #pragma unroll
                for (int c = 0; c < 4; c++) acc[s][a][b][c] = 0.f;

    // staging ids
    const int arow = tid >> 1, ac2 = (tid & 1) * 2;
    const int bp = tid & 15, bng = tid >> 4;
    const int bpp = (bp & 3) * 4 + (bp >> 2);
    const __half* aRow = A + (size_t)min(row0 + arow, M - 1) * lda;

    auto stage_A = [&](int s, int buf) {
        const __half* src = aRow + s * 32 + ac2 * 8;
        uint32_t dst = sA + (buf * ABUFU + arow * SROWU + ac2 * 4) * 4;
        CP_ASYNC16(dst, src);
        CP_ASYNC16(dst + 16, src + 8);
    };

    auto stage_B = [&](int s, int buf) {
        int k0g = s * 32 + 2 * bp;
        bool ok0 = (k0g < Kb), ok1 = (k0g + 1 < Kb);
        #pragma unroll
        for (int sl = 0; sl < NSLICE; sl++) {
            uint32_t* bb = Bbuf + (sl * 2 + buf) * ABUFU;
            int nbase = n0s + sl * 128 + bng * 8;
            #pragma unroll
            for (int h = 0; h < 2; h++) {
                int n4 = nbase + h * 4;
                float4 lo = ok0 ? *(const float4*)(B + (size_t)k0g * Nld + n4)
                                : make_float4(0.f, 0.f, 0.f, 0.f);
                float4 hi = ok1 ? *(const float4*)(B + (size_t)(k0g + 1) * Nld + n4)
                                : make_float4(0.f, 0.f, 0.f, 0.f);
                __half2 h0 = __floats2half2_rn(lo.x, hi.x);
                __half2 h1 = __floats2half2_rn(lo.y, hi.y);
                __half2 h2 = __floats2half2_rn(lo.z, hi.z);
                __half2 h3 = __floats2half2_rn(lo.w, hi.w);
                int nr = bng * 8 + h * 4;
                bb[(nr + 0) * SROWU + bpp] = *(uint32_t*)&h0;
                bb[(nr + 1) * SROWU + bpp] = *(uint32_t*)&h1;
                bb[(nr + 2) * SROWU + bpp] = *(uint32_t*)&h2;
                bb[(nr + 3) * SROWU + bpp] = *(uint32_t*)&h3;
            }
        }
    };

    stage_A(0, 0);
    CP_COMMIT();
    stage_B(0, 0);
    CP_WAIT0();
    __syncthreads();

    for (int s = 0; s < nstage; s++) {
        int cur = s & 1;
        bool more = (s + 1 < nstage);
        if (more) {
            stage_A(s + 1, cur ^ 1);
            CP_COMMIT();
            stage_B(s + 1, cur ^ 1);
        }

        // A fragments: [mf][ks][4]
        uint32_t af[2][2][4];
        const uint32_t* Ab = Abuf + cur * ABUFU;
        #pragma unroll
        for (int mf = 0; mf < 2; mf++) {
            int r0 = wM * 32 + mf * 16 + gq;
            const uint32_t* p0 = Ab + r0 * SROWU;
            const uint32_t* p1 = Ab + (r0 + 8) * SROWU;
            #pragma unroll
            for (int ks = 0; ks < 2; ks++) {
                af[mf][ks][0] = p0[tig + 8 * ks];
                af[mf][ks][1] = p1[tig + 8 * ks];
                af[mf][ks][2] = p0[tig + 4 + 8 * ks];
                af[mf][ks][3] = p1[tig + 4 + 8 * ks];
            }
        }
        #pragma unroll
        for (int sl = 0; sl < NSLICE; sl++) {
            const uint32_t* Bb = Bbuf + (sl * 2 + cur) * ABUFU;
            #pragma unroll
            for (int nf = 0; nf < 8; nf++) {
                int n = wN * 64 + nf * 8 + gq;
                uint4 bv = *(const uint4*)(Bb + n * SROWU + tig * 4);
                MMA_F16(acc[sl][0][nf], af[0][0][0], af[0][0][1], af[0][0][2], af[0][0][3], bv.x, bv.y);
                MMA_F16(acc[sl][1][nf], af[1][0][0], af[1][0][1], af[1][0][2], af[1][0][3], bv.x, bv.y);
                MMA_F16(acc[sl][0][nf], af[0][1][0], af[0][1][1], af[0][1][2], af[0][1][3], bv.z, bv.w);
                MMA_F16(acc[sl][1][nf], af[1][1][0], af[1][1][1], af[1][1][2], af[1][1][3], bv.z, bv.w);
            }
        }
        if (more) CP_WAIT0();
        __syncthreads();
    }

    if constexpr (EPI == 0) {
        #pragma unroll
        for (int mf = 0; mf < 2; mf++)
        #pragma unroll
        for (int rs = 0; rs < 2; rs++) {
            int r = row0 + wM * 32 + mf * 16 + rs * 8 + gq;
            if (r >= M) continue;
            #pragma unroll
            for (int nf = 0; nf < 8; nf++) {
                int nc = wN * 64 + nf * 8 + tig * 2;
                float v0 = acc[0][mf][nf][rs * 2 + 0] + __ldg(bias + n0s + nc);
                float v1 = acc[0][mf][nf][rs * 2 + 1] + __ldg(bias + n0s + nc + 1);
                v0 = v0 / (1.f + expf(-v0));
                v1 = v1 / (1.f + expf(-v1));
                *(__half2*)(C + (size_t)r * ldc + n0s + nc) = __floats2half2_rn(v0, v1);
            }
        }
    } else {
        #pragma unroll
        for (int mf = 0; mf < 2; mf++)
        #pragma unroll
        for (int rs = 0; rs < 2; rs++) {
            int e = row0 + wM * 32 + mf * 16 + rs * 8 + gq;
            if (e >= M) continue;
            int ii = nbrs[2 * e], jj = nbrs[2 * e + 1];
            float ux = unit[3 * e], uy = unit[3 * e + 1], uz = unit[3 * e + 2];
            #pragma unroll
            for (int nf = 0; nf < 8; nf++) {
                #pragma unroll
                for (int c = 0; c < 2; c++) {
                    int f = wN * 64 + nf * 8 + tig * 2 + c;
                    float s0 = acc[0][mf][nf][rs * 2 + c] + __ldg(bias + f);
                    float s1 = acc[1][mf][nf][rs * 2 + c] + __ldg(bias + 128 + f);
                    float s2 = acc[2][mf][nf][rs * 2 + c] + __ldg(bias + 256 + f);
                    atomicAdd(ds + (size_t)ii * FF + f, s1);
                    const float* vj = v_j + ((size_t)jj * FF + f) * 3;
                    float* dv = dvout + ((size_t)ii * FF + f) * 3;
                    atomicAdd(dv + 0, s2 * ux + s0 * vj[0]);
                    atomicAdd(dv + 1, s2 * uy + s0 * vj[1]);
                    atomicAdd(dv + 2, s2 * uz + s0 * vj[2]);
                }
            }
        }
    }
}

// ================= launch =================
extern "C" void kernel_launch(void* const* d_in, const int* in_sizes, int n_in,
                              void* d_out, int out_size) {
    const float* s_j  = (const float*)d_in[0];
    const float* v_j  = (const float*)d_in[1];
    const float* r_ij = (const float*)d_in[2];
    const int*   nbrs = (const int*)  d_in[3];
    const float* ln_g = (const float*)d_in[4];
    const float* ln_b = (const float*)d_in[5];
    const float* Wq   = (const float*)d_in[6];
    const float* bq   = (const float*)d_in[7];
    const float* Wk   = (const float*)d_in[8];
    const float* bk   = (const float*)d_in[9];
    const float* Wv   = (const float*)d_in[10];
    const float* bv   = (const float*)d_in[11];
    const float* Wdk  = (const float*)d_in[12];
    const float* bdk  = (const float*)d_in[13];
    const float* Wdv  = (const float*)d_in[14];
    const float* bdv  = (const float*)d_in[15];
    const float* Wd   = (const float*)d_in[16];
    const float* bd   = (const float*)d_in[17];
    float* out = (float*)d_out;

    float *x, *qkv, *unit;
    __half *rbf, *dkdv, *msg;
    cudaGetSymbolAddress((void**)&x,    g_x);
    cudaGetSymbolAddress((void**)&qkv,  g_qkv);
    cudaGetSymbolAddress((void**)&rbf,  g_rbf);
    cudaGetSymbolAddress((void**)&unit, g_unit);
    cudaGetSymbolAddress((void**)&dkdv, g_dkdv);
    cudaGetSymbolAddress((void**)&msg,  g_msg);

    const int SMEM_E0 = (2 + 1 * 2) * ABUFU * 4;   // 40960
    const int SMEM_E1 = (2 + 3 * 2) * ABUFU * 4;   // 81920
    cudaFuncSetAttribute(mma_fp16<0, 1>, cudaFuncAttributeMaxDynamicSharedMemorySize, SMEM_E0);
    cudaFuncSetAttribute(mma_fp16<1, 3>, cudaFuncAttributeMaxDynamicSharedMemorySize, SMEM_E1);

    const int OUT_ELEMS = NN * FF * 4;
    zero_kernel<<<(OUT_ELEMS + 255) / 256, 256>>>(out, OUT_ELEMS);

    ln_kernel<<<NN, 128>>>(s_j, ln_g, ln_b, x);

    dim3 gq3(12, (NN + 127) / 128);
    qkv_gemm<<<gq3, 256>>>(x, Wq, Wk, Wv, bq, bk, bv, qkv);

    edge_prep<<<(NE + 127) / 128, 128>>>(r_ij, rbf, unit);

    int mtiles = (NE + 127) / 128;   // 1954
    dim3 ge(4, mtiles);
    mma_fp16<0, 1><<<ge, 256, SMEM_E0>>>(rbf, Wdk, bdk, dkdv, 1024,
                                         nullptr, nullptr, nullptr, nullptr, nullptr,
                                         NE, 512, 50, RBFP, 2);
    mma_fp16<0, 1><<<ge, 256, SMEM_E0>>>(rbf, Wdv, bdv, dkdv + 512, 1024,
                                         nullptr, nullptr, nullptr, nullptr, nullptr,
                                         NE, 512, 50, RBFP, 2);

    attn_msg<<<NE, 128>>>(qkv, dkdv, nbrs, msg);

    mma_fp16<1, 3><<<mtiles, 256, SMEM_E1>>>(msg, Wd, bd, nullptr, 0,
                                             unit, v_j, nbrs, out, out + NN * FF,
                                             NE, 384, 512, 512, 16);
}

// round 6
// speedup vs baseline: 2.3899x; 1.0697x over previous
#include <cuda_runtime.h>
#include <cuda_fp16.h>
#include <math.h>
#include <stdint.h>

#define NN   10000
#define NE   250000
#define FF   128
#define NRBF 50
#define RBFP 64   // padded rbf stride (halves)

typedef unsigned long long ull;

// ---------------- scratch ----------------
__device__ float  g_x[NN * FF];
__device__ float  g_qkv[NN * 3 * 512];
__device__ __half g_rbf[(size_t)NE * RBFP];
__device__ float  g_unit[(size_t)NE * 3];
__device__ __half g_dkdv[(size_t)NE * 1024];
__device__ __half g_msg[(size_t)NE * 512];

#define FMA2(acc, a, b) asm("fma.rn.f32x2 %0, %1, %2, %0;" : "+l"(acc) : "l"(a), "l"(b))
#define PACK2(dst, f)   asm("mov.b64 %0, {%1, %1};" : "=l"(dst) : "f"(f))
#define UNPACK2(lo, hi, v) asm("mov.b64 {%0, %1}, %2;" : "=f"(lo), "=f"(hi) : "l"(v))

__device__ __forceinline__ uint32_t smem_u32(const void* p) {
    uint32_t a;
    asm("{ .reg .u64 t; cvta.to.shared.u64 t, %1; cvt.u32.u64 %0, t; }" : "=r"(a) : "l"(p));
    return a;
}
__device__ __forceinline__ float silu_f(float v) {
    return v / (1.f + __expf(-v));
}

#define MMA_F16(c, a0, a1, a2, a3, b0, b1)                                \
    asm volatile("mma.sync.aligned.m16n8k16.row.col.f32.f16.f16.f32 "     \
        "{%0,%1,%2,%3}, {%4,%5,%6,%7}, {%8,%9}, {%0,%1,%2,%3};"           \
        : "+f"((c)[0]), "+f"((c)[1]), "+f"((c)[2]), "+f"((c)[3])          \
        : "r"(a0), "r"(a1), "r"(a2), "r"(a3), "r"(b0), "r"(b1))

#define CP_ASYNC16(dst, src) \
    asm volatile("cp.async.ca.shared.global [%0], [%1], 16;" :: "r"(dst), "l"(src))
#define CP_COMMIT() asm volatile("cp.async.commit_group;" ::: "memory")
#define CP_WAIT0()  asm volatile("cp.async.wait_group 0;" ::: "memory")

// ================= small kernels =================
__global__ void zero_kernel(float* __restrict__ p, int n) {
    int i = blockIdx.x * blockDim.x + threadIdx.x;
    if (i < n) p[i] = 0.f;
}

__global__ void __launch_bounds__(128) ln_kernel(const float* __restrict__ s,
                                                 const float* __restrict__ gam,
                                                 const float* __restrict__ bet,
                                                 float* __restrict__ x) {
    int n = blockIdx.x, t = threadIdx.x;
    float v = s[(size_t)n * FF + t];
    float s1 = v, s2 = v * v;
    #pragma unroll
    for (int o = 16; o; o >>= 1) {
        s1 += __shfl_down_sync(0xffffffffu, s1, o);
        s2 += __shfl_down_sync(0xffffffffu, s2, o);
    }
    __shared__ float p1[4], p2[4], mv[2];
    if ((t & 31) == 0) { p1[t >> 5] = s1; p2[t >> 5] = s2; }
    __syncthreads();
    if (t == 0) {
        float a = p1[0] + p1[1] + p1[2] + p1[3];
        float c = p2[0] + p2[1] + p2[2] + p2[3];
        float m = a / 128.f;
        mv[0] = m;
        mv[1] = rsqrtf(c / 128.f - m * m + 1e-5f);
    }
    __syncthreads();
    x[(size_t)n * FF + t] = (v - mv[0]) * mv[1] * gam[t] + bet[t];
}

// edge_prep: register-buffered, vectorized 128B-row stores, __expf
__global__ void __launch_bounds__(256) edge_prep(const float* __restrict__ r,
                                                 __half* __restrict__ rbf,
                                                 float* __restrict__ unit) {
    int e = blockIdx.x * 256 + threadIdx.x;
    if (e >= NE) return;
    float x = __ldg(r + 3 * e), y = __ldg(r + 3 * e + 1), z = __ldg(r + 3 * e + 2);
    float d = sqrtf(x * x + y * y + z * z + 3e-15f);
    float inv = 1.f / d;
    unit[3 * e] = x * inv; unit[3 * e + 1] = y * inv; unit[3 * e + 2] = z * inv;
    const float width = 5.0f / 49.0f;
    const float gam = 0.5f / (width * width);
    __half2 buf[32];
    #pragma unroll
    for (int k2 = 0; k2 < 32; k2++) {
        int k0 = k2 * 2, k1 = k2 * 2 + 1;
        float d0 = d - (float)k0 * width;
        float d1 = d - (float)k1 * width;
        float v0 = (k0 < NRBF) ? __expf(-gam * d0 * d0) : 0.f;
        float v1 = (k1 < NRBF) ? __expf(-gam * d1 * d1) : 0.f;
        buf[k2] = __floats2half2_rn(v0, v1);
    }
    uint4* dst = (uint4*)(rbf + (size_t)e * RBFP);
    const uint4* src = (const uint4*)buf;
    #pragma unroll
    for (int q = 0; q < 8; q++) dst[q] = src[q];
}

// ================= qkv: fused 3-way f32x2 SGEMM =================
__global__ void __launch_bounds__(256, 2)
qkv_gemm(const float* __restrict__ Xin,
         const float* __restrict__ Wq, const float* __restrict__ Wk,
         const float* __restrict__ Wv,
         const float* __restrict__ bq, const float* __restrict__ bk,
         const float* __restrict__ bv,
         float* __restrict__ qkvout) {
    const int M = NN, N = 512, K = 128, lda = 128, ldc = 1536;
    int which = blockIdx.x >> 2;
    const float* B    = (which == 0) ? Wq : ((which == 1) ? Wk : Wv);
    const float* bias = (which == 0) ? bq : ((which == 1) ? bk : bv);
    float* C = qkvout + which * 512;
    int col0 = (blockIdx.x & 3) * 128;
    int row0 = blockIdx.y * 128;

    __shared__ float As[2][8][128];
    __shared__ float Bs[2][8][128];

    int t  = threadIdx.x;
    int ty = t >> 4, tx = t & 15;

    int arow = t >> 1;
    int acol = (t & 1) * 4;
    int am   = min(row0 + arow, M - 1);
    const float* Aptr = Xin + (size_t)am * lda + acol;

    int bk_ = t >> 5;
    int bn  = (t & 31) * 4;

    float4 ar, br;
    ar = *(const float4*)(Aptr);
    br = *(const float4*)(B + (size_t)bk_ * N + col0 + bn);

    As[0][acol + 0][arow] = ar.x;
    As[0][acol + 1][arow] = ar.y;
    As[0][acol + 2][arow] = ar.z;
    As[0][acol + 3][arow] = ar.w;
    *(float4*)&Bs[0][bk_][bn] = br;
    __syncthreads();

    ull acc[8][4];
    #pragma unroll
    for (int i = 0; i < 8; i++)
        #pragma unroll
        for (int j = 0; j < 4; j++) acc[i][j] = 0ULL;

    const int nstage = K >> 3;
    for (int s = 0; s < nstage; s++) {
        int cur = s & 1, nxt = cur ^ 1;
        bool more = (s + 1 < nstage);
        if (more) {
            int kk = (s + 1) << 3;
            ar = *(const float4*)(Aptr + kk);
            br = *(const float4*)(B + (size_t)(kk + bk_) * N + col0 + bn);
        }
        #pragma unroll
        for (int k = 0; k < 8; k++) {
            float4 a0 = *(float4*)&As[cur][k][ty * 8];
            float4 a1 = *(float4*)&As[cur][k][ty * 8 + 4];
            ulonglong2 b0 = *(ulonglong2*)&Bs[cur][k][tx * 8];
            ulonglong2 b1 = *(ulonglong2*)&Bs[cur][k][tx * 8 + 4];
            ull a2[8];
            PACK2(a2[0], a0.x); PACK2(a2[1], a0.y);
            PACK2(a2[2], a0.z); PACK2(a2[3], a0.w);
            PACK2(a2[4], a1.x); PACK2(a2[5], a1.y);
            PACK2(a2[6], a1.z); PACK2(a2[7], a1.w);
            #pragma unroll
            for (int i = 0; i < 8; i++) {
                FMA2(acc[i][0], a2[i], b0.x);
                FMA2(acc[i][1], a2[i], b0.y);
                FMA2(acc[i][2], a2[i], b1.x);
                FMA2(acc[i][3], a2[i], b1.y);
            }
        }
        if (more) {
            As[nxt][acol + 0][arow] = ar.x;
            As[nxt][acol + 1][arow] = ar.y;
            As[nxt][acol + 2][arow] = ar.z;
            As[nxt][acol + 3][arow] = ar.w;
            *(float4*)&Bs[nxt][bk_][bn] = br;
        }
        __syncthreads();
    }

    int colb = col0 + tx * 8;
    float4 bs0 = *(const float4*)(bias + colb);
    float4 bs1 = *(const float4*)(bias + colb + 4);
    #pragma unroll
    for (int i = 0; i < 8; i++) {
        int row = row0 + ty * 8 + i;
        if (row >= M) continue;
        float v[8];
        UNPACK2(v[0], v[1], acc[i][0]);
        UNPACK2(v[2], v[3], acc[i][1]);
        UNPACK2(v[4], v[5], acc[i][2]);
        UNPACK2(v[6], v[7], acc[i][3]);
        v[0] += bs0.x; v[1] += bs0.y; v[2] += bs0.z; v[3] += bs0.w;
        v[4] += bs1.x; v[5] += bs1.y; v[6] += bs1.z; v[7] += bs1.w;
        float* cp = C + (size_t)row * ldc + colb;
        *(float4*)cp       = make_float4(v[0], v[1], v[2], v[3]);
        *(float4*)(cp + 4) = make_float4(v[4], v[5], v[6], v[7]);
    }
}

// ================= attn + msg: warp-per-edge, vectorized =================
__global__ void __launch_bounds__(256) attn_msg(const float* __restrict__ qkv,
                                                const __half* __restrict__ dkdv,
                                                const int* __restrict__ nbrs,
                                                __half* __restrict__ msg) {
    int e = blockIdx.x * 8 + (threadIdx.x >> 5);
    if (e >= NE) return;
    int l = threadIdx.x & 31;
    int i = __ldg(nbrs + 2 * e), j = __ldg(nbrs + 2 * e + 1);
    const float4* q4 = (const float4*)(qkv + (size_t)i * 1536);
    const float4* k4 = (const float4*)(qkv + (size_t)j * 1536 + 512);
    const float4* v4 = (const float4*)(qkv + (size_t)j * 1536 + 1024);
    const uint2* dk2 = (const uint2*)(dkdv + (size_t)e * 1024);
    const uint2* dv2 = dk2 + 128;

    float4 qv[4], kv[4], vv[4];
    uint2 dkv[4], dvv[4];
    #pragma unroll
    for (int h = 0; h < 4; h++) {
        int idx = h * 32 + l;
        qv[h] = q4[idx]; kv[h] = k4[idx]; vv[h] = v4[idx];
        dkv[h] = dk2[idx]; dvv[h] = dv2[idx];
    }
    float p[4];
    #pragma unroll
    for (int h = 0; h < 4; h++) {
        float2 f0 = __half22float2(*(__half2*)&dkv[h].x);
        float2 f1 = __half22float2(*(__half2*)&dkv[h].y);
        p[h] = qv[h].x * kv[h].x * f0.x + qv[h].y * kv[h].y * f0.y
             + qv[h].z * kv[h].z * f1.x + qv[h].w * kv[h].w * f1.y;
    }
    #pragma unroll
    for (int o = 16; o; o >>= 1)
        #pragma unroll
        for (int h = 0; h < 4; h++) p[h] += __shfl_xor_sync(0xffffffffu, p[h], o);

    __half* mrow = msg + (size_t)e * 512;
    #pragma unroll
    for (int h = 0; h < 4; h++) {
        float at = silu_f(p[h]);
        float2 g0 = __half22float2(*(__half2*)&dvv[h].x);
        float2 g1 = __half22float2(*(__half2*)&dvv[h].y);
        __half2 m0 = __floats2half2_rn(vv[h].x * g0.x * at, vv[h].y * g0.y * at);
        __half2 m1 = __floats2half2_rn(vv[h].z * g1.x * at, vv[h].w * g1.y * at);
        uint2 o2;
        o2.x = *(uint32_t*)&m0;
        o2.y = *(uint32_t*)&m1;
        *(uint2*)(mrow + h * 128 + l * 4) = o2;
    }
}

// ================= fp16 mma GEMM =================
#define SROWU 20
#define ABUFU (128 * SROWU)

template <int EPI, int NSLICE>
__global__ void __launch_bounds__(256)
mma_fp16(const __half* __restrict__ A, const float* __restrict__ B,
         const float* __restrict__ bias, __half* __restrict__ C, int ldc,
         const float* __restrict__ unit, const float* __restrict__ v_j,
         const int* __restrict__ nbrs, float* __restrict__ ds,
         float* __restrict__ dvout,
         int M, int Nld, int Kb, int lda, int nstage) {
    extern __shared__ uint32_t sm[];
    uint32_t* Abuf = sm;
    uint32_t* Bbuf = sm + 2 * ABUFU;
    const uint32_t sA = smem_u32(sm);

    const int tid = threadIdx.x;
    const int wid = tid >> 5, lid = tid & 31;
    const int gq = lid >> 2, tig = lid & 3;
    const int wM = wid >> 1, wN = wid & 1;
    const int row0 = (EPI ? blockIdx.x : blockIdx.y) * 128;
    const int n0s  = (EPI ? 0 : blockIdx.x * 128);

    float acc[NSLICE][2][8][4];
    #pragma unroll
    for (int s = 0; s < NSLICE; s++)
        #pragma unroll
        for (int a = 0; a < 2; a++)
            #pragma unroll
            for (int b = 0; b < 8; b++)
                #pragma unroll
                for (int c = 0; c < 4; c++) acc[s][a][b][c] = 0.f;

    const int arow = tid >> 1, ac2 = (tid & 1) * 2;
    const int bp = tid & 15, bng = tid >> 4;
    const int bpp = (bp & 3) * 4 + (bp >> 2);
    const __half* aRow = A + (size_t)min(row0 + arow, M - 1) * lda;

    auto stage_A = [&](int s, int buf) {
        const __half* src = aRow + s * 32 + ac2 * 8;
        uint32_t dst = sA + (buf * ABUFU + arow * SROWU + ac2 * 4) * 4;
        CP_ASYNC16(dst, src);
        CP_ASYNC16(dst + 16, src + 8);
    };

    auto stage_B = [&](int s, int buf) {
        int k0g = s * 32 + 2 * bp;
        bool ok0 = (k0g < Kb), ok1 = (k0g + 1 < Kb);
        #pragma unroll
        for (int sl = 0; sl < NSLICE; sl++) {
            uint32_t* bb = Bbuf + (sl * 2 + buf) * ABUFU;
            int nbase = n0s + sl * 128 + bng * 8;
            #pragma unroll
            for (int h = 0; h < 2; h++) {
                int n4 = nbase + h * 4;
                float4 lo = ok0 ? *(const float4*)(B + (size_t)k0g * Nld + n4)
                                : make_float4(0.f, 0.f, 0.f, 0.f);
                float4 hi = ok1 ? *(const float4*)(B + (size_t)(k0g + 1) * Nld + n4)
                                : make_float4(0.f, 0.f, 0.f, 0.f);
                __half2 h0 = __floats2half2_rn(lo.x, hi.x);
                __half2 h1 = __floats2half2_rn(lo.y, hi.y);
                __half2 h2 = __floats2half2_rn(lo.z, hi.z);
                __half2 h3 = __floats2half2_rn(lo.w, hi.w);
                int nr = bng * 8 + h * 4;
                bb[(nr + 0) * SROWU + bpp] = *(uint32_t*)&h0;
                bb[(nr + 1) * SROWU + bpp] = *(uint32_t*)&h1;
                bb[(nr + 2) * SROWU + bpp] = *(uint32_t*)&h2;
                bb[(nr + 3) * SROWU + bpp] = *(uint32_t*)&h3;
            }
        }
    };

    stage_A(0, 0);
    CP_COMMIT();
    stage_B(0, 0);
    CP_WAIT0();
    __syncthreads();

    for (int s = 0; s < nstage; s++) {
        int cur = s & 1;
        bool more = (s + 1 < nstage);
        if (more) {
            stage_A(s + 1, cur ^ 1);
            CP_COMMIT();
            stage_B(s + 1, cur ^ 1);
        }

        uint32_t af[2][2][4];
        const uint32_t* Ab = Abuf + cur * ABUFU;
        #pragma unroll
        for (int mf = 0; mf < 2; mf++) {
            int r0 = wM * 32 + mf * 16 + gq;
            const uint32_t* p0 = Ab + r0 * SROWU;
            const uint32_t* p1 = Ab + (r0 + 8) * SROWU;
            #pragma unroll
            for (int ks = 0; ks < 2; ks++) {
                af[mf][ks][0] = p0[tig + 8 * ks];
                af[mf][ks][1] = p1[tig + 8 * ks];
                af[mf][ks][2] = p0[tig + 4 + 8 * ks];
                af[mf][ks][3] = p1[tig + 4 + 8 * ks];
            }
        }
        #pragma unroll
        for (int sl = 0; sl < NSLICE; sl++) {
            const uint32_t* Bb = Bbuf + (sl * 2 + cur) * ABUFU;
            #pragma unroll
            for (int nf = 0; nf < 8; nf++) {
                int n = wN * 64 + nf * 8 + gq;
                uint4 bv = *(const uint4*)(Bb + n * SROWU + tig * 4);
                MMA_F16(acc[sl][0][nf], af[0][0][0], af[0][0][1], af[0][0][2], af[0][0][3], bv.x, bv.y);
                MMA_F16(acc[sl][1][nf], af[1][0][0], af[1][0][1], af[1][0][2], af[1][0][3], bv.x, bv.y);
                MMA_F16(acc[sl][0][nf], af[0][1][0], af[0][1][1], af[0][1][2], af[0][1][3], bv.z, bv.w);
                MMA_F16(acc[sl][1][nf], af[1][1][0], af[1][1][1], af[1][1][2], af[1][1][3], bv.z, bv.w);
            }
        }
        if (more) CP_WAIT0();
        __syncthreads();
    }

    if constexpr (EPI == 0) {
        #pragma unroll
        for (int mf = 0; mf < 2; mf++)
        #pragma unroll
        for (int rs = 0; rs < 2; rs++) {
            int r = row0 + wM * 32 + mf * 16 + rs * 8 + gq;
            if (r >= M) continue;
            #pragma unroll
            for (int nf = 0; nf < 8; nf++) {
                int nc = wN * 64 + nf * 8 + tig * 2;
                float v0 = silu_f(acc[0][mf][nf][rs * 2 + 0] + __ldg(bias + n0s + nc));
                float v1 = silu_f(acc[0][mf][nf][rs * 2 + 1] + __ldg(bias + n0s + nc + 1));
                *(__half2*)(C + (size_t)r * ldc + n0s + nc) = __floats2half2_rn(v0, v1);
            }
        }
    } else {
        #pragma unroll
        for (int mf = 0; mf < 2; mf++)
        #pragma unroll
        for (int rs = 0; rs < 2; rs++) {
            int e = row0 + wM * 32 + mf * 16 + rs * 8 + gq;
            if (e >= M) continue;
            int ii = nbrs[2 * e], jj = nbrs[2 * e + 1];
            float ux = unit[3 * e], uy = unit[3 * e + 1], uz = unit[3 * e + 2];
            #pragma unroll
            for (int nf = 0; nf < 8; nf++) {
                #pragma unroll
                for (int c = 0; c < 2; c++) {
                    int f = wN * 64 + nf * 8 + tig * 2 + c;
                    float s0 = acc[0][mf][nf][rs * 2 + c] + __ldg(bias + f);
                    float s1 = acc[1][mf][nf][rs * 2 + c] + __ldg(bias + 128 + f);
                    float s2 = acc[2][mf][nf][rs * 2 + c] + __ldg(bias + 256 + f);
                    atomicAdd(ds + (size_t)ii * FF + f, s1);
                    const float* vj = v_j + ((size_t)jj * FF + f) * 3;
                    float* dv = dvout + ((size_t)ii * FF + f) * 3;
                    atomicAdd(dv + 0, s2 * ux + s0 * vj[0]);
                    atomicAdd(dv + 1, s2 * uy + s0 * vj[1]);
                    atomicAdd(dv + 2, s2 * uz + s0 * vj[2]);
                }
            }
        }
    }
}

// ================= launch =================
extern "C" void kernel_launch(void* const* d_in, const int* in_sizes, int n_in,
                              void* d_out, int out_size) {
    const float* s_j  = (const float*)d_in[0];
    const float* v_j  = (const float*)d_in[1];
    const float* r_ij = (const float*)d_in[2];
    const int*   nbrs = (const int*)  d_in[3];
    const float* ln_g = (const float*)d_in[4];
    const float* ln_b = (const float*)d_in[5];
    const float* Wq   = (const float*)d_in[6];
    const float* bq   = (const float*)d_in[7];
    const float* Wk   = (const float*)d_in[8];
    const float* bk   = (const float*)d_in[9];
    const float* Wv   = (const float*)d_in[10];
    const float* bv   = (const float*)d_in[11];
    const float* Wdk  = (const float*)d_in[12];
    const float* bdk  = (const float*)d_in[13];
    const float* Wdv  = (const float*)d_in[14];
    const float* bdv  = (const float*)d_in[15];
    const float* Wd   = (const float*)d_in[16];
    const float* bd   = (const float*)d_in[17];
    float* out = (float*)d_out;

    float *x, *qkv, *unit;
    __half *rbf, *dkdv, *msg;
    cudaGetSymbolAddress((void**)&x,    g_x);
    cudaGetSymbolAddress((void**)&qkv,  g_qkv);
    cudaGetSymbolAddress((void**)&rbf,  g_rbf);
    cudaGetSymbolAddress((void**)&unit, g_unit);
    cudaGetSymbolAddress((void**)&dkdv, g_dkdv);
    cudaGetSymbolAddress((void**)&msg,  g_msg);

    const int SMEM_E0 = (2 + 1 * 2) * ABUFU * 4;   // 40960
    const int SMEM_E1 = (2 + 3 * 2) * ABUFU * 4;   // 81920
    cudaFuncSetAttribute(mma_fp16<0, 1>, cudaFuncAttributeMaxDynamicSharedMemorySize, SMEM_E0);
    cudaFuncSetAttribute(mma_fp16<1, 3>, cudaFuncAttributeMaxDynamicSharedMemorySize, SMEM_E1);

    const int OUT_ELEMS = NN * FF * 4;
    zero_kernel<<<(OUT_ELEMS + 255) / 256, 256>>>(out, OUT_ELEMS);

    ln_kernel<<<NN, 128>>>(s_j, ln_g, ln_b, x);

    dim3 gq3(12, (NN + 127) / 128);
    qkv_gemm<<<gq3, 256>>>(x, Wq, Wk, Wv, bq, bk, bv, qkv);

    edge_prep<<<(NE + 255) / 256, 256>>>(r_ij, rbf, unit);

    int mtiles = (NE + 127) / 128;   // 1954
    dim3 ge(4, mtiles);
    mma_fp16<0, 1><<<ge, 256, SMEM_E0>>>(rbf, Wdk, bdk, dkdv, 1024,
                                         nullptr, nullptr, nullptr, nullptr, nullptr,
                                         NE, 512, 50, RBFP, 2);
    mma_fp16<0, 1><<<ge, 256, SMEM_E0>>>(rbf, Wdv, bdv, dkdv + 512, 1024,
                                         nullptr, nullptr, nullptr, nullptr, nullptr,
                                         NE, 512, 50, RBFP, 2);

    attn_msg<<<(NE + 7) / 8, 256>>>(qkv, dkdv, nbrs, msg);

    mma_fp16<1, 3><<<mtiles, 256, SMEM_E1>>>(msg, Wd, bd, nullptr, 0,
                                             unit, v_j, nbrs, out, out + NN * FF,
                                             NE, 384, 512, 512, 16);
}